// round 9
// baseline (speedup 1.0000x reference)
#include <cuda_runtime.h>
#include <cuda_bf16.h>
#include <math.h>
#include <stdint.h>

#define NN   50000
#define EE   150000
#define DD   256
#define NP   768          // P columns = 3 * 256
#define SCAN_BLOCKS 49    // ceil(50000/1024)

// ------------------------ device scratch (no allocs allowed) ------------------
__device__ int   g_deg [3 * NN];
__device__ int   g_cur [3 * NN];
__device__ int   g_rs  [3 * (NN + 1)];
__device__ int   g_bsum[3 * SCAN_BLOCKS];
__device__ int   g_boff[3 * SCAN_BLOCKS];
__device__ int   g_snbr[3 * 2 * EE];

__device__ __nv_bfloat16 g_Shi[(size_t)NN * DD];
__device__ __nv_bfloat16 g_Slo[(size_t)NN * DD];
__device__ __nv_bfloat16 g_Wahi[(size_t)NP * DD];   // [n=r*256+d][k]
__device__ __nv_bfloat16 g_Walo[(size_t)NP * DD];
__device__ __nv_bfloat16 g_Wvhi[(size_t)DD * NP];   // [n=d][k'=r*256+k]
__device__ __nv_bfloat16 g_Wvlo[(size_t)DD * NP];
__device__ float         g_P  [(size_t)NN * NP];    // 153.6 MB
__device__ __nv_bfloat16 g_Thi[(size_t)NN * NP];
__device__ __nv_bfloat16 g_Tlo[(size_t)NN * NP];

// ------------------------ PTX helpers ----------------------------------------
__device__ __forceinline__ uint32_t smem_u32(const void* p) {
    return (uint32_t)__cvta_generic_to_shared(p);
}
__device__ __forceinline__ void cp16(uint32_t dst, const void* src, int srcsz) {
    asm volatile("cp.async.cg.shared.global [%0], [%1], 16, %2;"
                 :: "r"(dst), "l"(src), "r"(srcsz) : "memory");
}
#define CP_COMMIT() asm volatile("cp.async.commit_group;" ::: "memory")
#define CP_WAIT(n)  asm volatile("cp.async.wait_group %0;" :: "n"(n) : "memory")

#define LDSM4(r, addr) asm volatile( \
    "ldmatrix.sync.aligned.m8n8.x4.shared.b16 {%0,%1,%2,%3}, [%4];" \
    : "=r"((r)[0]), "=r"((r)[1]), "=r"((r)[2]), "=r"((r)[3]) : "r"(addr))

#define MMA16816(d, a, b) asm volatile( \
    "mma.sync.aligned.m16n8k16.row.col.f32.bf16.bf16.f32 " \
    "{%0,%1,%2,%3}, {%4,%5,%6,%7}, {%8,%9}, {%0,%1,%2,%3};" \
    : "+f"((d)[0]), "+f"((d)[1]), "+f"((d)[2]), "+f"((d)[3]) \
    : "r"((a)[0]), "r"((a)[1]), "r"((a)[2]), "r"((a)[3]), \
      "r"((b)[0]), "r"((b)[1]))

// ------------------------ CSR build ------------------------------------------
__global__ void zero_kernel() {
    int idx = blockIdx.x * blockDim.x + threadIdx.x;
    if (idx < 3 * NN) { g_deg[idx] = 0; g_cur[idx] = 0; }
}

__global__ void degree_kernel(const int* __restrict__ e0,
                              const int* __restrict__ e1,
                              const int* __restrict__ e2) {
    int idx = blockIdx.x * blockDim.x + threadIdx.x;
    if (idx >= 3 * 2 * EE) return;
    int r = idx / (2 * EE);
    int k = idx - r * (2 * EE);
    const int* e = (r == 0) ? e0 : ((r == 1) ? e1 : e2);
    atomicAdd(&g_deg[r * NN + e[k]], 1);
}

// block-local exclusive scan; writes block sums
__global__ void scan_local() {
    __shared__ int buf[1024];
    int r = blockIdx.y;
    int tid = threadIdx.x;
    int idx = blockIdx.x * 1024 + tid;
    int v = (idx < NN) ? g_deg[r * NN + idx] : 0;
    buf[tid] = v;
    __syncthreads();
    for (int off = 1; off < 1024; off <<= 1) {
        int t = (tid >= off) ? buf[tid - off] : 0;
        __syncthreads();
        buf[tid] += t;
        __syncthreads();
    }
    if (idx < NN) g_rs[r * (NN + 1) + idx] = buf[tid] - v;
    if (tid == 1023) g_bsum[r * SCAN_BLOCKS + blockIdx.x] = buf[1023];
}

// warp-parallel scan of block sums (one warp per relation)
__global__ void scan_bsums() {
    int r = threadIdx.x >> 5;
    int lane = threadIdx.x & 31;
    if (r >= 3) return;
    int carry = 0;
    for (int b0 = 0; b0 < SCAN_BLOCKS; b0 += 32) {
        int idx = b0 + lane;
        int orig = (idx < SCAN_BLOCKS) ? g_bsum[r * SCAN_BLOCKS + idx] : 0;
        int v = orig;
#pragma unroll
        for (int off = 1; off < 32; off <<= 1) {
            int t = __shfl_up_sync(0xFFFFFFFFu, v, off);
            if (lane >= off) v += t;
        }
        if (idx < SCAN_BLOCKS) g_boff[r * SCAN_BLOCKS + idx] = carry + v - orig;
        carry += __shfl_sync(0xFFFFFFFFu, v, 31);
    }
    if (lane == 0) g_rs[r * (NN + 1) + NN] = carry;
}

__global__ void scan_add() {
    int r = blockIdx.y;
    int idx = blockIdx.x * 1024 + threadIdx.x;
    if (idx < NN) g_rs[r * (NN + 1) + idx] += g_boff[r * SCAN_BLOCKS + blockIdx.x];
}

__global__ void fill_kernel(const int* __restrict__ e0,
                            const int* __restrict__ e1,
                            const int* __restrict__ e2) {
    int idx = blockIdx.x * blockDim.x + threadIdx.x;
    if (idx >= 3 * EE) return;
    int r = idx / EE;
    int k = idx - r * EE;
    const int* e = (r == 0) ? e0 : ((r == 1) ? e1 : e2);
    int a = e[2 * k], b = e[2 * k + 1];
    int pa = g_rs[r * (NN + 1) + a] + atomicAdd(&g_cur[r * NN + a], 1);
    g_snbr[r * 2 * EE + pa] = b;
    int pb = g_rs[r * (NN + 1) + b] + atomicAdd(&g_cur[r * NN + b], 1);
    g_snbr[r * 2 * EE + pb] = a;
}

// ------------------------ bf16 hi/lo conversions -----------------------------
__device__ __forceinline__ void split4(float4 v, __nv_bfloat16* hp, __nv_bfloat16* lp) {
    __nv_bfloat16 h0 = __float2bfloat16(v.x), h1 = __float2bfloat16(v.y);
    __nv_bfloat16 h2 = __float2bfloat16(v.z), h3 = __float2bfloat16(v.w);
    __nv_bfloat16 l0 = __float2bfloat16(v.x - __bfloat162float(h0));
    __nv_bfloat16 l1 = __float2bfloat16(v.y - __bfloat162float(h1));
    __nv_bfloat16 l2 = __float2bfloat16(v.z - __bfloat162float(h2));
    __nv_bfloat16 l3 = __float2bfloat16(v.w - __bfloat162float(h3));
    ((__nv_bfloat162*)hp)[0] = __halves2bfloat162(h0, h1);
    ((__nv_bfloat162*)hp)[1] = __halves2bfloat162(h2, h3);
    ((__nv_bfloat162*)lp)[0] = __halves2bfloat162(l0, l1);
    ((__nv_bfloat162*)lp)[1] = __halves2bfloat162(l2, l3);
}

__global__ void convertS_kernel(const float* __restrict__ S) {
    int idx = blockIdx.x * blockDim.x + threadIdx.x;      // float4 index
    if (idx >= NN * DD / 4) return;
    float4 v = ((const float4*)S)[idx];
    split4(v, g_Shi + idx * 4, g_Slo + idx * 4);
}

// Wa[n=r*256+d][k] = A_r[k][d] = sum_j WQ_r[j][k] * WK_r[j][d]
__global__ void build_wa(const float* __restrict__ WQ,
                         const float* __restrict__ WK) {
    int b = blockIdx.x;            // 0..767
    int r = b >> 8;
    int k = b & 255;
    int d = threadIdx.x;           // 0..255
    const float* wq = WQ + r * 65536;
    const float* wk = WK + r * 65536;
    float acc = 0.f;
#pragma unroll 8
    for (int j = 0; j < 256; j++)
        acc += wq[j * 256 + k] * wk[j * 256 + d];
    __nv_bfloat16 h = __float2bfloat16(acc);
    __nv_bfloat16 l = __float2bfloat16(acc - __bfloat162float(h));
    g_Wahi[(size_t)(r * 256 + d) * DD + k] = h;
    g_Walo[(size_t)(r * 256 + d) * DD + k] = l;
}

// Wv[n=d][k'=r*256+k] = W_r[d][k]
__global__ void build_wv(const float* __restrict__ W) {
    int idx = blockIdx.x * blockDim.x + threadIdx.x;
    if (idx >= DD * NP) return;
    int d  = idx / NP;
    int rk = idx - d * NP;
    int r  = rk >> 8;
    int k  = rk & 255;
    float w = W[r * 65536 + d * 256 + k];
    __nv_bfloat16 h = __float2bfloat16(w);
    g_Wvhi[idx] = h;
    g_Wvlo[idx] = __float2bfloat16(w - __bfloat162float(h));
}

// ------------------------ mma.sync bf16x3 GEMM (3-stage pipeline) ------------
// C[M,N] = A[M,K] @ B[N,K]^T, fp32 out.
// BM=128, BN=128, BK=32, 256 threads (2x4 warps, warp tile 64x32).
// Warp-staggered ks order de-phases LDSM bursts from MMA bursts across warps.
#define STG      32768                  // per-stage: A 16K | B 16K
#define GEMM_SMEM (3 * STG)             // 98304

__global__ void __launch_bounds__(256)
mma_gemm(const __nv_bfloat16* __restrict__ Ahi, const __nv_bfloat16* __restrict__ Alo,
         const __nv_bfloat16* __restrict__ Bhi, const __nv_bfloat16* __restrict__ Blo,
         float* __restrict__ C, int M, int K, int N, int relu) {
    extern __shared__ char smem[];
    const uint32_t sbase = smem_u32(smem);
    const int t = threadIdx.x;
    const int w = t >> 5, l = t & 31;
    const int wm = (w >> 2) * 64;    // warp M offset
    const int wn = (w & 3) * 32;     // warp N offset
    const int bm = blockIdx.y * 128;
    const int n0 = blockIdx.x * 128;
    const int ksFirst = w & 1;       // stagger: odd warps do ks=1 first

    const int lrow = t >> 1;
    const int half = t & 1;
    const __nv_bfloat16* aRow = (half ? Alo : Ahi);
    const __nv_bfloat16* bRow = (half ? Blo : Bhi);
    int mrow = bm + lrow;
    int av = (mrow < M) ? 16 : 0;
    aRow += (size_t)((mrow < M) ? mrow : 0) * K;
    bRow += (size_t)(n0 + lrow) * K;
    const uint32_t aDst = sbase + lrow * 128;
    const uint32_t bDst = sbase + 16384 + lrow * 128;

    float acc[4][4][4];
#pragma unroll
    for (int i = 0; i < 4; i++)
#pragma unroll
        for (int j = 0; j < 4; j++)
#pragma unroll
            for (int q = 0; q < 4; q++) acc[i][j][q] = 0.f;

    auto load_stage = [&](int s, int kt) {
        uint32_t so = (uint32_t)s * STG;
#pragma unroll
        for (int c = 0; c < 4; c++) {
            int chunk = half * 4 + c;
            uint32_t sw = (uint32_t)((chunk ^ (lrow & 7)) << 4);
            cp16(aDst + so + sw, aRow + kt * 32 + c * 8, av);
            cp16(bDst + so + sw, bRow + kt * 32 + c * 8, 16);
        }
    };

    auto compute = [&](int s) {
        uint32_t aB = sbase + (uint32_t)s * STG;
        uint32_t bB = aB + 16384;
#pragma unroll
        for (int kk = 0; kk < 2; kk++) {
            int ks = ksFirst ^ kk;
            uint32_t Af[2][4][4];
#pragma unroll
            for (int im = 0; im < 4; im++) {
                int row = wm + im * 16 + (l & 15);
                int ch = ks * 2 + (l >> 4);
                LDSM4(Af[0][im], aB + row * 128 + ((ch ^ (row & 7)) << 4));
                LDSM4(Af[1][im], aB + row * 128 + (((ch + 4) ^ (row & 7)) << 4));
            }
            uint32_t Bf[2][4][2];
#pragma unroll
            for (int p = 0; p < 2; p++) {
                int row = wn + p * 16 + (l & 7) + ((l >> 4) & 1) * 8;
                int ch = ks * 2 + ((l >> 3) & 1);
                uint32_t r4[4];
                LDSM4(r4, bB + row * 128 + ((ch ^ (row & 7)) << 4));
                Bf[0][p * 2][0] = r4[0]; Bf[0][p * 2][1] = r4[1];
                Bf[0][p * 2 + 1][0] = r4[2]; Bf[0][p * 2 + 1][1] = r4[3];
                LDSM4(r4, bB + row * 128 + (((ch + 4) ^ (row & 7)) << 4));
                Bf[1][p * 2][0] = r4[0]; Bf[1][p * 2][1] = r4[1];
                Bf[1][p * 2 + 1][0] = r4[2]; Bf[1][p * 2 + 1][1] = r4[3];
            }
#pragma unroll
            for (int im = 0; im < 4; im++)
#pragma unroll
                for (int in = 0; in < 4; in++)
                    MMA16816(acc[im][in], Af[0][im], Bf[0][in]);
#pragma unroll
            for (int im = 0; im < 4; im++)
#pragma unroll
                for (int in = 0; in < 4; in++)
                    MMA16816(acc[im][in], Af[0][im], Bf[1][in]);
#pragma unroll
            for (int im = 0; im < 4; im++)
#pragma unroll
                for (int in = 0; in < 4; in++)
                    MMA16816(acc[im][in], Af[1][im], Bf[0][in]);
        }
    };

    const int KT = K / 32;
    load_stage(0, 0); CP_COMMIT();
    load_stage(1, 1); CP_COMMIT();
    int s = 0;
    for (int kt = 0; kt < KT; kt++) {
        if (kt < KT - 1) { CP_WAIT(1); } else { CP_WAIT(0); }
        __syncthreads();                 // prior compute done; stage kt resident
        if (kt + 2 < KT) {
            int s2 = s + 2; if (s2 >= 3) s2 -= 3;
            load_stage(s2, kt + 2);
            CP_COMMIT();
        }
        compute(s);
        if (++s == 3) s = 0;
    }

    // epilogue
#pragma unroll
    for (int im = 0; im < 4; im++) {
        int r0 = bm + wm + im * 16 + (l >> 2);
#pragma unroll
        for (int in = 0; in < 4; in++) {
            int cc = n0 + wn + in * 8 + (l & 3) * 2;
            float* a4 = acc[im][in];
            if (relu) {
                a4[0] = fmaxf(a4[0], 0.f); a4[1] = fmaxf(a4[1], 0.f);
                a4[2] = fmaxf(a4[2], 0.f); a4[3] = fmaxf(a4[3], 0.f);
            }
            if (r0 < M)
                *(float2*)(C + (size_t)r0 * N + cc) = make_float2(a4[0], a4[1]);
            if (r0 + 8 < M)
                *(float2*)(C + (size_t)(r0 + 8) * N + cc) = make_float2(a4[2], a4[3]);
        }
    }
}

// ------------------------ fused attention aggregation (single pass) ----------
__global__ __launch_bounds__(256)
void agg_kernel(const float* __restrict__ S) {
    int w = threadIdx.x >> 5;
    int l = threadIdx.x & 31;
    int i = blockIdx.x * 8 + w;
    if (i >= NN) return;

    for (int r = 0; r < 3; r++) {
        float4 acc0 = make_float4(0.f, 0.f, 0.f, 0.f);
        float4 acc1 = make_float4(0.f, 0.f, 0.f, 0.f);
        int start = g_rs[r * (NN + 1) + i];
        int deg   = g_rs[r * (NN + 1) + i + 1] - start;

        if (deg > 0) {
            const float* Pb = g_P + (size_t)i * NP + r * 256;
            float4 p0 = *(const float4*)(Pb + 4 * l);
            float4 p1 = *(const float4*)(Pb + 128 + 4 * l);
            const int* nb = g_snbr + r * 2 * EE + start;

            float z = 0.f;
            for (int j = 0; j < deg; j++) {
                int nbr = nb[j];
                const float* Sr = S + (size_t)nbr * DD;
                float4 s0 = *(const float4*)(Sr + 4 * l);
                float4 s1 = *(const float4*)(Sr + 128 + 4 * l);
                float d = p0.x * s0.x + p0.y * s0.y + p0.z * s0.z + p0.w * s0.w
                        + p1.x * s1.x + p1.y * s1.y + p1.z * s1.z + p1.w * s1.w;
#pragma unroll
                for (int off = 16; off; off >>= 1)
                    d += __shfl_xor_sync(0xFFFFFFFFu, d, off);
                float e = __expf(d * 0.125f);
                z += e;
                acc0.x += e * s0.x; acc0.y += e * s0.y;
                acc0.z += e * s0.z; acc0.w += e * s0.w;
                acc1.x += e * s1.x; acc1.y += e * s1.y;
                acc1.z += e * s1.z; acc1.w += e * s1.w;
            }
            float zi = 1.f / z;
            acc0.x *= zi; acc0.y *= zi; acc0.z *= zi; acc0.w *= zi;
            acc1.x *= zi; acc1.y *= zi; acc1.z *= zi; acc1.w *= zi;
        }
        size_t base = (size_t)i * NP + r * 256;
        split4(acc0, g_Thi + base + 4 * l,       g_Tlo + base + 4 * l);
        split4(acc1, g_Thi + base + 128 + 4 * l, g_Tlo + base + 128 + 4 * l);
    }
}

// ------------------------ launch --------------------------------------------
extern "C" void kernel_launch(void* const* d_in, const int* in_sizes, int n_in,
                              void* d_out, int out_size) {
    const float* S  = (const float*)d_in[0];
    const int*   et = (const int*)d_in[1];
    const int*   ec = (const int*)d_in[2];
    const int*   e2 = (const int*)d_in[3];
    const float* W  = (const float*)d_in[4];
    const float* WQ = (const float*)d_in[5];
    const float* WK = (const float*)d_in[6];
    float* out = (float*)d_out;

    static bool init = false;
    static __nv_bfloat16 *pShi, *pSlo, *pWahi, *pWalo, *pWvhi, *pWvlo, *pThi, *pTlo;
    static float* pP;
    static cudaStream_t s1, s2;
    static cudaEvent_t evFork, evJoin, evW;
    if (!init) {
        cudaGetSymbolAddress((void**)&pShi,  g_Shi);
        cudaGetSymbolAddress((void**)&pSlo,  g_Slo);
        cudaGetSymbolAddress((void**)&pWahi, g_Wahi);
        cudaGetSymbolAddress((void**)&pWalo, g_Walo);
        cudaGetSymbolAddress((void**)&pWvhi, g_Wvhi);
        cudaGetSymbolAddress((void**)&pWvlo, g_Wvlo);
        cudaGetSymbolAddress((void**)&pThi,  g_Thi);
        cudaGetSymbolAddress((void**)&pTlo,  g_Tlo);
        cudaGetSymbolAddress((void**)&pP,    g_P);
        cudaFuncSetAttribute(mma_gemm, cudaFuncAttributeMaxDynamicSharedMemorySize,
                             GEMM_SMEM);
        cudaStreamCreateWithFlags(&s1, cudaStreamNonBlocking);
        cudaStreamCreateWithFlags(&s2, cudaStreamNonBlocking);
        cudaEventCreateWithFlags(&evFork, cudaEventDisableTiming);
        cudaEventCreateWithFlags(&evJoin, cudaEventDisableTiming);
        cudaEventCreateWithFlags(&evW,    cudaEventDisableTiming);
        init = true;
    }

    // fork
    cudaEventRecord(evFork, 0);
    cudaStreamWaitEvent(s1, evFork, 0);
    cudaStreamWaitEvent(s2, evFork, 0);

    // s1: CSR build chain (independent of GEMM path)
    zero_kernel<<<(3 * NN + 255) / 256, 256, 0, s1>>>();
    degree_kernel<<<(3 * 2 * EE + 255) / 256, 256, 0, s1>>>(et, ec, e2);
    scan_local<<<dim3(SCAN_BLOCKS, 3), 1024, 0, s1>>>();
    scan_bsums<<<1, 96, 0, s1>>>();
    scan_add<<<dim3(SCAN_BLOCKS, 3), 1024, 0, s1>>>();
    fill_kernel<<<(3 * EE + 255) / 256, 256, 0, s1>>>(et, ec, e2);
    cudaEventRecord(evJoin, s1);

    // s2: weight prep (independent of convertS)
    build_wa<<<NP, 256, 0, s2>>>(WQ, WK);
    build_wv<<<(DD * NP + 255) / 256, 256, 0, s2>>>(W);
    cudaEventRecord(evW, s2);

    // main: S conversion, then GEMM1 (needs Shi/Slo + Wa)
    convertS_kernel<<<(NN * DD / 4 + 255) / 256, 256>>>(S);
    cudaStreamWaitEvent(0, evW, 0);
    mma_gemm<<<dim3(NP / 128, (NN + 127) / 128), 256, GEMM_SMEM>>>(
        pShi, pSlo, pWahi, pWalo, pP, NN, DD, NP, 0);

    // join: agg needs CSR + P
    cudaStreamWaitEvent(0, evJoin, 0);
    agg_kernel<<<(NN + 7) / 8, 256>>>(S);
    // GEMM2: out = relu(T @ Wv^T)  (50000 x 256, K=768)
    mma_gemm<<<dim3(DD / 128, (NN + 127) / 128), 256, GEMM_SMEM>>>(
        pThi, pTlo, pWvhi, pWvlo, out, NN, NP, DD, 1);
}

// round 10
// speedup vs baseline: 1.0531x; 1.0531x over previous
#include <cuda_runtime.h>
#include <cuda_bf16.h>
#include <math.h>
#include <stdint.h>

#define NN   50000
#define EE   150000
#define DD   256
#define NP   768          // P columns = 3 * 256
#define SCAN_BLOCKS 49    // ceil(50000/1024)
#define MSPLIT 25088      // 196 * 128, M pipeline split point

// ------------------------ device scratch (no allocs allowed) ------------------
__device__ int   g_deg [3 * NN];
__device__ int   g_cur [3 * NN];
__device__ int   g_rs  [3 * (NN + 1)];
__device__ int   g_bsum[3 * SCAN_BLOCKS];
__device__ int   g_boff[3 * SCAN_BLOCKS];
__device__ int   g_snbr[3 * 2 * EE];

__device__ __nv_bfloat16 g_Shi[(size_t)NN * DD];
__device__ __nv_bfloat16 g_Slo[(size_t)NN * DD];
__device__ __nv_bfloat16 g_Wahi[(size_t)NP * DD];   // [n=r*256+d][k]
__device__ __nv_bfloat16 g_Walo[(size_t)NP * DD];
__device__ __nv_bfloat16 g_Wvhi[(size_t)DD * NP];   // [n=d][k'=r*256+k]
__device__ __nv_bfloat16 g_Wvlo[(size_t)DD * NP];
__device__ float         g_P  [(size_t)NN * NP];    // 153.6 MB
__device__ __nv_bfloat16 g_Thi[(size_t)NN * NP];
__device__ __nv_bfloat16 g_Tlo[(size_t)NN * NP];

// ------------------------ PTX helpers ----------------------------------------
__device__ __forceinline__ uint32_t smem_u32(const void* p) {
    return (uint32_t)__cvta_generic_to_shared(p);
}
__device__ __forceinline__ void cp16(uint32_t dst, const void* src, int srcsz) {
    asm volatile("cp.async.cg.shared.global [%0], [%1], 16, %2;"
                 :: "r"(dst), "l"(src), "r"(srcsz) : "memory");
}
#define CP_COMMIT() asm volatile("cp.async.commit_group;" ::: "memory")
#define CP_WAIT(n)  asm volatile("cp.async.wait_group %0;" :: "n"(n) : "memory")

#define LDSM4(r, addr) asm volatile( \
    "ldmatrix.sync.aligned.m8n8.x4.shared.b16 {%0,%1,%2,%3}, [%4];" \
    : "=r"((r)[0]), "=r"((r)[1]), "=r"((r)[2]), "=r"((r)[3]) : "r"(addr))

#define MMA16816(d, a, b) asm volatile( \
    "mma.sync.aligned.m16n8k16.row.col.f32.bf16.bf16.f32 " \
    "{%0,%1,%2,%3}, {%4,%5,%6,%7}, {%8,%9}, {%0,%1,%2,%3};" \
    : "+f"((d)[0]), "+f"((d)[1]), "+f"((d)[2]), "+f"((d)[3]) \
    : "r"((a)[0]), "r"((a)[1]), "r"((a)[2]), "r"((a)[3]), \
      "r"((b)[0]), "r"((b)[1]))

// ------------------------ CSR build ------------------------------------------
__global__ void zero_kernel() {
    int idx = blockIdx.x * blockDim.x + threadIdx.x;
    if (idx < 3 * NN) { g_deg[idx] = 0; g_cur[idx] = 0; }
}

__global__ void degree_kernel(const int* __restrict__ e0,
                              const int* __restrict__ e1,
                              const int* __restrict__ e2) {
    int idx = blockIdx.x * blockDim.x + threadIdx.x;
    if (idx >= 3 * 2 * EE) return;
    int r = idx / (2 * EE);
    int k = idx - r * (2 * EE);
    const int* e = (r == 0) ? e0 : ((r == 1) ? e1 : e2);
    atomicAdd(&g_deg[r * NN + e[k]], 1);
}

__global__ void scan_local() {
    __shared__ int buf[1024];
    int r = blockIdx.y;
    int tid = threadIdx.x;
    int idx = blockIdx.x * 1024 + tid;
    int v = (idx < NN) ? g_deg[r * NN + idx] : 0;
    buf[tid] = v;
    __syncthreads();
    for (int off = 1; off < 1024; off <<= 1) {
        int t = (tid >= off) ? buf[tid - off] : 0;
        __syncthreads();
        buf[tid] += t;
        __syncthreads();
    }
    if (idx < NN) g_rs[r * (NN + 1) + idx] = buf[tid] - v;
    if (tid == 1023) g_bsum[r * SCAN_BLOCKS + blockIdx.x] = buf[1023];
}

__global__ void scan_bsums() {
    int r = threadIdx.x >> 5;
    int lane = threadIdx.x & 31;
    if (r >= 3) return;
    int carry = 0;
    for (int b0 = 0; b0 < SCAN_BLOCKS; b0 += 32) {
        int idx = b0 + lane;
        int orig = (idx < SCAN_BLOCKS) ? g_bsum[r * SCAN_BLOCKS + idx] : 0;
        int v = orig;
#pragma unroll
        for (int off = 1; off < 32; off <<= 1) {
            int t = __shfl_up_sync(0xFFFFFFFFu, v, off);
            if (lane >= off) v += t;
        }
        if (idx < SCAN_BLOCKS) g_boff[r * SCAN_BLOCKS + idx] = carry + v - orig;
        carry += __shfl_sync(0xFFFFFFFFu, v, 31);
    }
    if (lane == 0) g_rs[r * (NN + 1) + NN] = carry;
}

__global__ void scan_add() {
    int r = blockIdx.y;
    int idx = blockIdx.x * 1024 + threadIdx.x;
    if (idx < NN) g_rs[r * (NN + 1) + idx] += g_boff[r * SCAN_BLOCKS + blockIdx.x];
}

__global__ void fill_kernel(const int* __restrict__ e0,
                            const int* __restrict__ e1,
                            const int* __restrict__ e2) {
    int idx = blockIdx.x * blockDim.x + threadIdx.x;
    if (idx >= 3 * EE) return;
    int r = idx / EE;
    int k = idx - r * EE;
    const int* e = (r == 0) ? e0 : ((r == 1) ? e1 : e2);
    int a = e[2 * k], b = e[2 * k + 1];
    int pa = g_rs[r * (NN + 1) + a] + atomicAdd(&g_cur[r * NN + a], 1);
    g_snbr[r * 2 * EE + pa] = b;
    int pb = g_rs[r * (NN + 1) + b] + atomicAdd(&g_cur[r * NN + b], 1);
    g_snbr[r * 2 * EE + pb] = a;
}

// ------------------------ bf16 hi/lo conversions -----------------------------
__device__ __forceinline__ void split4(float4 v, __nv_bfloat16* hp, __nv_bfloat16* lp) {
    __nv_bfloat16 h0 = __float2bfloat16(v.x), h1 = __float2bfloat16(v.y);
    __nv_bfloat16 h2 = __float2bfloat16(v.z), h3 = __float2bfloat16(v.w);
    __nv_bfloat16 l0 = __float2bfloat16(v.x - __bfloat162float(h0));
    __nv_bfloat16 l1 = __float2bfloat16(v.y - __bfloat162float(h1));
    __nv_bfloat16 l2 = __float2bfloat16(v.z - __bfloat162float(h2));
    __nv_bfloat16 l3 = __float2bfloat16(v.w - __bfloat162float(h3));
    ((__nv_bfloat162*)hp)[0] = __halves2bfloat162(h0, h1);
    ((__nv_bfloat162*)hp)[1] = __halves2bfloat162(h2, h3);
    ((__nv_bfloat162*)lp)[0] = __halves2bfloat162(l0, l1);
    ((__nv_bfloat162*)lp)[1] = __halves2bfloat162(l2, l3);
}

__global__ void convertS_kernel(const float* __restrict__ S) {
    int idx = blockIdx.x * blockDim.x + threadIdx.x;      // float4 index
    if (idx >= NN * DD / 4) return;
    float4 v = ((const float4*)S)[idx];
    split4(v, g_Shi + idx * 4, g_Slo + idx * 4);
}

// Wa[n=r*256+d][k] = A_r[k][d] = sum_j WQ_r[j][k] * WK_r[j][d]
__global__ void build_wa(const float* __restrict__ WQ,
                         const float* __restrict__ WK) {
    int b = blockIdx.x;            // 0..767
    int r = b >> 8;
    int k = b & 255;
    int d = threadIdx.x;           // 0..255
    const float* wq = WQ + r * 65536;
    const float* wk = WK + r * 65536;
    float acc = 0.f;
#pragma unroll 8
    for (int j = 0; j < 256; j++)
        acc += wq[j * 256 + k] * wk[j * 256 + d];
    __nv_bfloat16 h = __float2bfloat16(acc);
    __nv_bfloat16 l = __float2bfloat16(acc - __bfloat162float(h));
    g_Wahi[(size_t)(r * 256 + d) * DD + k] = h;
    g_Walo[(size_t)(r * 256 + d) * DD + k] = l;
}

// Wv[n=d][k'=r*256+k] = W_r[d][k]
__global__ void build_wv(const float* __restrict__ W) {
    int idx = blockIdx.x * blockDim.x + threadIdx.x;
    if (idx >= DD * NP) return;
    int d  = idx / NP;
    int rk = idx - d * NP;
    int r  = rk >> 8;
    int k  = rk & 255;
    float w = W[r * 65536 + d * 256 + k];
    __nv_bfloat16 h = __float2bfloat16(w);
    g_Wvhi[idx] = h;
    g_Wvlo[idx] = __float2bfloat16(w - __bfloat162float(h));
}

// ------------------------ mma.sync bf16x3 GEMM (3-stage pipeline) ------------
// C[rows mbase..mEnd, N] = A[rows, K] @ B[N,K]^T, fp32 out. Row-sliced via mbase.
#define STG      32768
#define GEMM_SMEM (3 * STG)

__global__ void __launch_bounds__(256)
mma_gemm(const __nv_bfloat16* __restrict__ Ahi, const __nv_bfloat16* __restrict__ Alo,
         const __nv_bfloat16* __restrict__ Bhi, const __nv_bfloat16* __restrict__ Blo,
         float* __restrict__ C, int mbase, int mEnd, int K, int N, int relu) {
    extern __shared__ char smem[];
    const uint32_t sbase = smem_u32(smem);
    const int t = threadIdx.x;
    const int w = t >> 5, l = t & 31;
    const int wm = (w >> 2) * 64;
    const int wn = (w & 3) * 32;
    const int bm = mbase + blockIdx.y * 128;
    const int n0 = blockIdx.x * 128;

    const int lrow = t >> 1;
    const int half = t & 1;
    const __nv_bfloat16* aRow = (half ? Alo : Ahi);
    const __nv_bfloat16* bRow = (half ? Blo : Bhi);
    int mrow = bm + lrow;
    int av = (mrow < mEnd) ? 16 : 0;
    aRow += (size_t)((mrow < mEnd) ? mrow : 0) * K;
    bRow += (size_t)(n0 + lrow) * K;
    const uint32_t aDst = sbase + lrow * 128;
    const uint32_t bDst = sbase + 16384 + lrow * 128;

    float acc[4][4][4];
#pragma unroll
    for (int i = 0; i < 4; i++)
#pragma unroll
        for (int j = 0; j < 4; j++)
#pragma unroll
            for (int q = 0; q < 4; q++) acc[i][j][q] = 0.f;

    auto load_stage = [&](int s, int kt) {
        uint32_t so = (uint32_t)s * STG;
#pragma unroll
        for (int c = 0; c < 4; c++) {
            int chunk = half * 4 + c;
            uint32_t sw = (uint32_t)((chunk ^ (lrow & 7)) << 4);
            cp16(aDst + so + sw, aRow + kt * 32 + c * 8, av);
            cp16(bDst + so + sw, bRow + kt * 32 + c * 8, 16);
        }
    };

    auto compute = [&](int s) {
        uint32_t aB = sbase + (uint32_t)s * STG;
        uint32_t bB = aB + 16384;
#pragma unroll
        for (int ks = 0; ks < 2; ks++) {
            uint32_t Af[2][4][4];
#pragma unroll
            for (int im = 0; im < 4; im++) {
                int row = wm + im * 16 + (l & 15);
                int ch = ks * 2 + (l >> 4);
                LDSM4(Af[0][im], aB + row * 128 + ((ch ^ (row & 7)) << 4));
                LDSM4(Af[1][im], aB + row * 128 + (((ch + 4) ^ (row & 7)) << 4));
            }
            uint32_t Bf[2][4][2];
#pragma unroll
            for (int p = 0; p < 2; p++) {
                int row = wn + p * 16 + (l & 7) + ((l >> 4) & 1) * 8;
                int ch = ks * 2 + ((l >> 3) & 1);
                uint32_t r4[4];
                LDSM4(r4, bB + row * 128 + ((ch ^ (row & 7)) << 4));
                Bf[0][p * 2][0] = r4[0]; Bf[0][p * 2][1] = r4[1];
                Bf[0][p * 2 + 1][0] = r4[2]; Bf[0][p * 2 + 1][1] = r4[3];
                LDSM4(r4, bB + row * 128 + (((ch + 4) ^ (row & 7)) << 4));
                Bf[1][p * 2][0] = r4[0]; Bf[1][p * 2][1] = r4[1];
                Bf[1][p * 2 + 1][0] = r4[2]; Bf[1][p * 2 + 1][1] = r4[3];
            }
#pragma unroll
            for (int im = 0; im < 4; im++)
#pragma unroll
                for (int in = 0; in < 4; in++)
                    MMA16816(acc[im][in], Af[0][im], Bf[0][in]);
#pragma unroll
            for (int im = 0; im < 4; im++)
#pragma unroll
                for (int in = 0; in < 4; in++)
                    MMA16816(acc[im][in], Af[0][im], Bf[1][in]);
#pragma unroll
            for (int im = 0; im < 4; im++)
#pragma unroll
                for (int in = 0; in < 4; in++)
                    MMA16816(acc[im][in], Af[1][im], Bf[0][in]);
        }
    };

    const int KT = K / 32;
    load_stage(0, 0); CP_COMMIT();
    load_stage(1, 1); CP_COMMIT();
    int s = 0;
    for (int kt = 0; kt < KT; kt++) {
        if (kt < KT - 1) { CP_WAIT(1); } else { CP_WAIT(0); }
        __syncthreads();
        if (kt + 2 < KT) {
            int s2 = s + 2; if (s2 >= 3) s2 -= 3;
            load_stage(s2, kt + 2);
            CP_COMMIT();
        }
        compute(s);
        if (++s == 3) s = 0;
    }

#pragma unroll
    for (int im = 0; im < 4; im++) {
        int r0 = bm + wm + im * 16 + (l >> 2);
#pragma unroll
        for (int in = 0; in < 4; in++) {
            int cc = n0 + wn + in * 8 + (l & 3) * 2;
            float* a4 = acc[im][in];
            if (relu) {
                a4[0] = fmaxf(a4[0], 0.f); a4[1] = fmaxf(a4[1], 0.f);
                a4[2] = fmaxf(a4[2], 0.f); a4[3] = fmaxf(a4[3], 0.f);
            }
            if (r0 < mEnd)
                *(float2*)(C + (size_t)r0 * N + cc) = make_float2(a4[0], a4[1]);
            if (r0 + 8 < mEnd)
                *(float2*)(C + (size_t)(r0 + 8) * N + cc) = make_float2(a4[2], a4[3]);
        }
    }
}

// ------------------------ fused attention aggregation (single pass) ----------
__global__ __launch_bounds__(256)
void agg_kernel(const float* __restrict__ S, int nbase, int nEnd) {
    int w = threadIdx.x >> 5;
    int l = threadIdx.x & 31;
    int i = nbase + blockIdx.x * 8 + w;
    if (i >= nEnd) return;

    for (int r = 0; r < 3; r++) {
        float4 acc0 = make_float4(0.f, 0.f, 0.f, 0.f);
        float4 acc1 = make_float4(0.f, 0.f, 0.f, 0.f);
        int start = g_rs[r * (NN + 1) + i];
        int deg   = g_rs[r * (NN + 1) + i + 1] - start;

        if (deg > 0) {
            const float* Pb = g_P + (size_t)i * NP + r * 256;
            float4 p0 = *(const float4*)(Pb + 4 * l);
            float4 p1 = *(const float4*)(Pb + 128 + 4 * l);
            const int* nb = g_snbr + r * 2 * EE + start;

            float z = 0.f;
            for (int j = 0; j < deg; j++) {
                int nbr = nb[j];
                const float* Sr = S + (size_t)nbr * DD;
                float4 s0 = *(const float4*)(Sr + 4 * l);
                float4 s1 = *(const float4*)(Sr + 128 + 4 * l);
                float d = p0.x * s0.x + p0.y * s0.y + p0.z * s0.z + p0.w * s0.w
                        + p1.x * s1.x + p1.y * s1.y + p1.z * s1.z + p1.w * s1.w;
#pragma unroll
                for (int off = 16; off; off >>= 1)
                    d += __shfl_xor_sync(0xFFFFFFFFu, d, off);
                float e = __expf(d * 0.125f);
                z += e;
                acc0.x += e * s0.x; acc0.y += e * s0.y;
                acc0.z += e * s0.z; acc0.w += e * s0.w;
                acc1.x += e * s1.x; acc1.y += e * s1.y;
                acc1.z += e * s1.z; acc1.w += e * s1.w;
            }
            float zi = 1.f / z;
            acc0.x *= zi; acc0.y *= zi; acc0.z *= zi; acc0.w *= zi;
            acc1.x *= zi; acc1.y *= zi; acc1.z *= zi; acc1.w *= zi;
        }
        size_t base = (size_t)i * NP + r * 256;
        split4(acc0, g_Thi + base + 4 * l,       g_Tlo + base + 4 * l);
        split4(acc1, g_Thi + base + 128 + 4 * l, g_Tlo + base + 128 + 4 * l);
    }
}

// ------------------------ launch --------------------------------------------
extern "C" void kernel_launch(void* const* d_in, const int* in_sizes, int n_in,
                              void* d_out, int out_size) {
    const float* S  = (const float*)d_in[0];
    const int*   et = (const int*)d_in[1];
    const int*   ec = (const int*)d_in[2];
    const int*   e2 = (const int*)d_in[3];
    const float* W  = (const float*)d_in[4];
    const float* WQ = (const float*)d_in[5];
    const float* WK = (const float*)d_in[6];
    float* out = (float*)d_out;

    static bool init = false;
    static __nv_bfloat16 *pShi, *pSlo, *pWahi, *pWalo, *pWvhi, *pWvlo, *pThi, *pTlo;
    static float* pP;
    static cudaStream_t s1, s2, s3;
    static cudaEvent_t evFork, evCSR, evW, evG1a, evG1b, evAa, evAb;
    if (!init) {
        cudaGetSymbolAddress((void**)&pShi,  g_Shi);
        cudaGetSymbolAddress((void**)&pSlo,  g_Slo);
        cudaGetSymbolAddress((void**)&pWahi, g_Wahi);
        cudaGetSymbolAddress((void**)&pWalo, g_Walo);
        cudaGetSymbolAddress((void**)&pWvhi, g_Wvhi);
        cudaGetSymbolAddress((void**)&pWvlo, g_Wvlo);
        cudaGetSymbolAddress((void**)&pThi,  g_Thi);
        cudaGetSymbolAddress((void**)&pTlo,  g_Tlo);
        cudaGetSymbolAddress((void**)&pP,    g_P);
        cudaFuncSetAttribute(mma_gemm, cudaFuncAttributeMaxDynamicSharedMemorySize,
                             GEMM_SMEM);
        cudaStreamCreateWithFlags(&s1, cudaStreamNonBlocking);
        cudaStreamCreateWithFlags(&s2, cudaStreamNonBlocking);
        cudaStreamCreateWithFlags(&s3, cudaStreamNonBlocking);
        cudaEventCreateWithFlags(&evFork, cudaEventDisableTiming);
        cudaEventCreateWithFlags(&evCSR,  cudaEventDisableTiming);
        cudaEventCreateWithFlags(&evW,    cudaEventDisableTiming);
        cudaEventCreateWithFlags(&evG1a,  cudaEventDisableTiming);
        cudaEventCreateWithFlags(&evG1b,  cudaEventDisableTiming);
        cudaEventCreateWithFlags(&evAa,   cudaEventDisableTiming);
        cudaEventCreateWithFlags(&evAb,   cudaEventDisableTiming);
        init = true;
    }

    const int MB_A = MSPLIT / 128;                 // 196 blocks
    const int MB_B = (NN - MSPLIT + 127) / 128;    // 195 blocks
    const int NB_A = (MSPLIT + 7) / 8;             // agg blocks slice a
    const int NB_B = (NN - MSPLIT + 7) / 8;

    // fork
    cudaEventRecord(evFork, 0);
    cudaStreamWaitEvent(s1, evFork, 0);
    cudaStreamWaitEvent(s2, evFork, 0);
    cudaStreamWaitEvent(s3, evFork, 0);

    // s1: CSR build chain
    zero_kernel<<<(3 * NN + 255) / 256, 256, 0, s1>>>();
    degree_kernel<<<(3 * 2 * EE + 255) / 256, 256, 0, s1>>>(et, ec, e2);
    scan_local<<<dim3(SCAN_BLOCKS, 3), 1024, 0, s1>>>();
    scan_bsums<<<1, 96, 0, s1>>>();
    scan_add<<<dim3(SCAN_BLOCKS, 3), 1024, 0, s1>>>();
    fill_kernel<<<(3 * EE + 255) / 256, 256, 0, s1>>>(et, ec, e2);
    cudaEventRecord(evCSR, s1);

    // s2: weight prep
    build_wa<<<NP, 256, 0, s2>>>(WQ, WK);
    build_wv<<<(DD * NP + 255) / 256, 256, 0, s2>>>(W);
    cudaEventRecord(evW, s2);

    // main: convert S, then GEMM1 in two M-slices
    convertS_kernel<<<(NN * DD / 4 + 255) / 256, 256>>>(S);
    cudaStreamWaitEvent(0, evW, 0);
    mma_gemm<<<dim3(NP / 128, MB_A), 256, GEMM_SMEM>>>(
        pShi, pSlo, pWahi, pWalo, pP, 0, MSPLIT, DD, NP, 0);
    cudaEventRecord(evG1a, 0);
    mma_gemm<<<dim3(NP / 128, MB_B), 256, GEMM_SMEM>>>(
        pShi, pSlo, pWahi, pWalo, pP, MSPLIT, NN, DD, NP, 0);
    cudaEventRecord(evG1b, 0);

    // s3: agg slices (overlap with GEMM1b / GEMM2a on main)
    cudaStreamWaitEvent(s3, evCSR, 0);
    cudaStreamWaitEvent(s3, evG1a, 0);
    agg_kernel<<<NB_A, 256, 0, s3>>>(S, 0, MSPLIT);
    cudaEventRecord(evAa, s3);
    cudaStreamWaitEvent(s3, evG1b, 0);
    agg_kernel<<<NB_B, 256, 0, s3>>>(S, MSPLIT, NN);
    cudaEventRecord(evAb, s3);

    // main: GEMM2 in two M-slices, each gated on its agg slice
    cudaStreamWaitEvent(0, evAa, 0);
    mma_gemm<<<dim3(DD / 128, MB_A), 256, GEMM_SMEM>>>(
        pThi, pTlo, pWvhi, pWvlo, out, 0, MSPLIT, NP, DD, 1);
    cudaStreamWaitEvent(0, evAb, 0);
    mma_gemm<<<dim3(DD / 128, MB_B), 256, GEMM_SMEM>>>(
        pThi, pTlo, pWvhi, pWvlo, out, MSPLIT, NN, NP, DD, 1);
}